// round 14
// baseline (speedup 1.0000x reference)
#include <cuda_runtime.h>
#include <cuda_fp16.h>
#include <cstdint>

#define BATCH 32
#define SEQ   16384
#define CIN   64
#define NF    64
#define KW    9
#define TOUT  (SEQ - KW + 1)          // 16376
#define TTILE 512
#define TILES_PER_B 32
#define NTILES (BATCH * TILES_PER_B)  // 1024
#define XROWS (TTILE + KW - 1)        // 520
#define NCTA  148
#define NTHR  640                     // 16 MMA warps + 4 producer warps
#define NMMAW 16
#define NPROD 128                     // producer threads
#define NCHUNK (XROWS * 8)            // 4160 16B-smem chunks per tile

// smem layout (from 1024B-aligned base)
#define WS_OFF    0
#define WS_BYTES  (KW * 64 * 128)            // 73728
#define XSB       (XROWS * 128)              // 66560
#define XS0_OFF   WS_BYTES                   // 73728
#define XS1_OFF   (XS0_OFF + XSB)            // 140288
#define BIAS_OFF  (XS1_OFF + XSB)            // 206848
#define SMEM_BYTES (BIAS_OFF + 256 + 1024)   // 208128 -> 1 CTA/SM

__device__ __align__(16) unsigned char wt_img[WS_BYTES];

static __device__ __forceinline__ uint32_t swz(uint32_t o) { return o ^ ((o >> 3) & 0x70); }

static __device__ __forceinline__ uint32_t smem_u32(const void* p) {
    uint32_t a;
    asm("{ .reg .u64 t; cvta.to.shared.u64 t, %1; cvt.u32.u64 %0, t; }" : "=r"(a) : "l"(p));
    return a;
}
static __device__ __forceinline__ void ldsm_x4(uint32_t& r0, uint32_t& r1, uint32_t& r2, uint32_t& r3, uint32_t addr) {
    asm volatile("ldmatrix.sync.aligned.m8n8.x4.shared.b16 {%0,%1,%2,%3}, [%4];"
                 : "=r"(r0), "=r"(r1), "=r"(r2), "=r"(r3) : "r"(addr));
}
static __device__ __forceinline__ void ldsm_x4t(uint32_t& r0, uint32_t& r1, uint32_t& r2, uint32_t& r3, uint32_t addr) {
    asm volatile("ldmatrix.sync.aligned.m8n8.x4.trans.shared.b16 {%0,%1,%2,%3}, [%4];"
                 : "=r"(r0), "=r"(r1), "=r"(r2), "=r"(r3) : "r"(addr));
}
static __device__ __forceinline__ void mma16816(float* d, const uint32_t* a, const uint32_t* b) {
    asm volatile("mma.sync.aligned.m16n8k16.row.col.f32.f16.f16.f32 "
                 "{%0,%1,%2,%3}, {%4,%5,%6,%7}, {%8,%9}, {%0,%1,%2,%3};"
                 : "+f"(d[0]), "+f"(d[1]), "+f"(d[2]), "+f"(d[3])
                 : "r"(a[0]), "r"(a[1]), "r"(a[2]), "r"(a[3]), "r"(b[0]), "r"(b[1]));
}
static __device__ __forceinline__ uint4 cvt8(const float4 a0, const float4 a1) {
    __half2 h0 = __floats2half2_rn(a0.x, a0.y);
    __half2 h1 = __floats2half2_rn(a0.z, a0.w);
    __half2 h2 = __floats2half2_rn(a1.x, a1.y);
    __half2 h3 = __floats2half2_rn(a1.z, a1.w);
    uint4 v;
    v.x = *(uint32_t*)&h0; v.y = *(uint32_t*)&h1;
    v.z = *(uint32_t*)&h2; v.w = *(uint32_t*)&h3;
    return v;
}

// ---- prep: w fp32 [f][k][c] -> fp16 image [k][c][f], SW128 per 8KB tap tile --
__global__ void prep_w_kernel(const float* __restrict__ w) {
    int i = blockIdx.x * 256 + threadIdx.x;
    if (i < NF * KW * CIN) {
        int f = i / (KW * CIN);
        int k = (i / CIN) % KW;
        int c = i % CIN;
        *reinterpret_cast<__half*>(wt_img + k * 8192 + swz((uint32_t)(c * 128 + f * 2))) = __float2half_rn(w[i]);
    }
}

// ---- main persistent kernel: 16 MMA warps (32r x 64f) + 4 producer warps -----
__global__ __launch_bounds__(NTHR, 1) void conv_hmma_kernel(const float* __restrict__ x,
                                                            const float* __restrict__ bias,
                                                            float* __restrict__ out) {
    extern __shared__ char smem_raw[];
    const uint32_t raw = smem_u32(smem_raw);
    const uint32_t sb  = (raw + 1023u) & ~1023u;
    char* base = smem_raw + (sb - raw);
    const int tid  = threadIdx.x;
    const int lane = tid & 31;
    const int wid  = tid >> 5;

    // copy w image + bias into smem (once)
    for (int i = tid; i < WS_BYTES / 16; i += NTHR)
        *(uint4*)(base + WS_OFF + i * 16) = *(const uint4*)(wt_img + i * 16);
    if (tid < NF) *(float*)(base + BIAS_OFF + tid * 4) = bias[tid];

    // ---- prologue: all threads stage first tile (fp32 LDG -> cvt -> STS)
    {
        const int tile = blockIdx.x;
        const int t0 = (tile & 31) << 9;
        const float* xb = x + ((size_t)(tile >> 5) << 20);
        for (int q = tid; q < NCHUNK; q += NTHR) {
            const int r = q >> 3, c0 = (q & 7) << 3;
            const int t = t0 + r;
            uint4 v = make_uint4(0u, 0u, 0u, 0u);
            if (t < SEQ) {
                const float4 a0 = *(const float4*)(xb + (size_t)t * CIN + c0);
                const float4 a1 = *(const float4*)(xb + (size_t)t * CIN + c0 + 4);
                v = cvt8(a0, a1);
            }
            *(uint4*)(base + XS0_OFF + swz((uint32_t)(r * 128 + c0 * 2))) = v;
        }
    }
    __syncthreads();

    if (wid < NMMAW) {
        // ================= MMA warps =================
        const int warp_m = wid;                       // 32 rows each
        const int row8   = (lane & 7) + ((lane >> 3) & 1) * 8;
        const int half16 = (lane >> 4);
        const uint32_t a_base = (uint32_t)(row8 * 128 + half16 * 16);
        const uint32_t b_base = (uint32_t)(row8 * 128 + half16 * 16);
        const int g  = lane >> 2;
        const int tg = lane & 3;
        const uint32_t ws_addr = sb + WS_OFF;

        int buf = 0;
        for (int tile = blockIdx.x; tile < NTILES; tile += NCTA) {
            const int b  = tile >> 5;
            const int t0 = (tile & 31) << 9;
            const uint32_t xs = sb + (buf ? XS1_OFF : XS0_OFF);

            float acc[2][8][4];
#pragma unroll
            for (int mt = 0; mt < 2; mt++)
#pragma unroll
                for (int nt = 0; nt < 8; nt++)
#pragma unroll
                    for (int j = 0; j < 4; j++) acc[mt][nt][j] = 0.0f;

#pragma unroll 3
            for (int k = 0; k < KW; k++) {
                const uint32_t a_row0 = (uint32_t)((warp_m * 32 + k) * 128);
                const uint32_t w_tap  = ws_addr + (uint32_t)(k * 8192);
#pragma unroll
                for (int cc = 0; cc < 4; cc++) {
                    // all 6 loads up front: 4x B, 2x A
                    uint32_t bf[8][2];
#pragma unroll
                    for (int p = 0; p < 4; p++) {
                        const uint32_t off = (uint32_t)(cc * 16 * 128) + (uint32_t)(p * 32) + b_base;
                        uint32_t r0, r1, r2, r3;
                        ldsm_x4t(r0, r1, r2, r3, w_tap + swz(off));
                        bf[p * 2 + 0][0] = r0; bf[p * 2 + 0][1] = r1;
                        bf[p * 2 + 1][0] = r2; bf[p * 2 + 1][1] = r3;
                    }
                    uint32_t af[2][4];
#pragma unroll
                    for (int mt = 0; mt < 2; mt++) {
                        const uint32_t off = a_row0 + (uint32_t)(mt * 16 * 128) + (uint32_t)(cc * 32) + a_base;
                        ldsm_x4(af[mt][0], af[mt][1], af[mt][2], af[mt][3], xs + swz(off));
                    }
#pragma unroll
                    for (int mt = 0; mt < 2; mt++)
#pragma unroll
                        for (int nt = 0; nt < 8; nt++)
                            mma16816(acc[mt][nt], af[mt], bf[nt]);
                }
            }

            // ---- epilogue: bias (smem) + direct STG
#pragma unroll
            for (int mt = 0; mt < 2; mt++) {
                const int trow = t0 + warp_m * 32 + mt * 16 + g;
#pragma unroll
                for (int half = 0; half < 2; half++) {
                    const int t = trow + half * 8;
                    if (t < TOUT) {
                        float* o = out + ((size_t)b * TOUT + t) * NF;
#pragma unroll
                        for (int nt = 0; nt < 8; nt++) {
                            const float2 bv = *(const float2*)(base + BIAS_OFF + (nt * 8 + tg * 2) * 4);
                            float2 v;
                            v.x = acc[mt][nt][half * 2 + 0] + bv.x;
                            v.y = acc[mt][nt][half * 2 + 1] + bv.y;
                            *(float2*)(o + nt * 8 + tg * 2) = v;
                        }
                    }
                }
            }
            __syncthreads();           // join with producers; buffers swap
            buf ^= 1;
        }
    } else {
        // ================= producer warps =================
        const int ptid = tid - NMMAW * 32;     // 0..127
        int buf = 0;
        for (int tile = blockIdx.x; tile < NTILES; tile += NCTA) {
            const int nxt = tile + NCTA;
            if (nxt < NTILES) {
                const int nt0 = (nxt & 31) << 9;
                const float* nxb = x + ((size_t)(nxt >> 5) << 20);
                char* xd = base + (buf ? XS0_OFF : XS1_OFF);
                for (int q = ptid; q < NCHUNK; q += NPROD) {
                    const int r = q >> 3, c0 = (q & 7) << 3;
                    const int t = nt0 + r;
                    uint4 v = make_uint4(0u, 0u, 0u, 0u);
                    if (t < SEQ) {
                        const float4 a0 = *(const float4*)(nxb + (size_t)t * CIN + c0);
                        const float4 a1 = *(const float4*)(nxb + (size_t)t * CIN + c0 + 4);
                        v = cvt8(a0, a1);
                    }
                    *(uint4*)(xd + swz((uint32_t)(r * 128 + c0 * 2))) = v;
                }
            }
            __syncthreads();           // join with MMA warps
            buf ^= 1;
        }
    }
}

extern "C" void kernel_launch(void* const* d_in, const int* in_sizes, int n_in,
                              void* d_out, int out_size) {
    const float* x    = (const float*)d_in[0];
    const float* w    = (const float*)d_in[1];
    const float* bias = (const float*)d_in[2];
    float* out = (float*)d_out;

    cudaFuncSetAttribute(conv_hmma_kernel, cudaFuncAttributeMaxDynamicSharedMemorySize, SMEM_BYTES);

    prep_w_kernel<<<(NF * KW * CIN + 255) / 256, 256>>>(w);
    conv_hmma_kernel<<<NCTA, NTHR, SMEM_BYTES>>>(x, bias, out);
}

// round 15
// speedup vs baseline: 1.2405x; 1.2405x over previous
#include <cuda_runtime.h>
#include <cuda_fp16.h>
#include <cstdint>

#define BATCH 32
#define SEQ   16384
#define CIN   64
#define NF    64
#define KW    9
#define TOUT  (SEQ - KW + 1)          // 16376
#define TTILE 512
#define TILES_PER_B 32
#define NTILES (BATCH * TILES_PER_B)  // 1024
#define XROWS (TTILE + KW - 1)        // 520
#define NCTA  148
#define NTHR  512
#define NCHUNK (XROWS * 8)            // 4160 16B-smem chunks per tile
#define SLICE_CH 464                  // chunks per tap-slice (9*464 >= 4160); <= NTHR

// smem layout (from 1024B-aligned base)
#define WS_OFF    0
#define WS_BYTES  (KW * 64 * 128)            // 73728
#define XSB       (XROWS * 128)              // 66560
#define XS0_OFF   WS_BYTES                   // 73728
#define XS1_OFF   (XS0_OFF + XSB)            // 140288
#define BIAS_OFF  (XS1_OFF + XSB)            // 206848
#define SMEM_BYTES (BIAS_OFF + 256 + 1024)   // 208128 -> 1 CTA/SM

__device__ __align__(16) unsigned char wt_img[WS_BYTES];

static __device__ __forceinline__ uint32_t swz(uint32_t o) { return o ^ ((o >> 3) & 0x70); }

static __device__ __forceinline__ uint32_t smem_u32(const void* p) {
    uint32_t a;
    asm("{ .reg .u64 t; cvta.to.shared.u64 t, %1; cvt.u32.u64 %0, t; }" : "=r"(a) : "l"(p));
    return a;
}
static __device__ __forceinline__ void ldsm_x4(uint32_t& r0, uint32_t& r1, uint32_t& r2, uint32_t& r3, uint32_t addr) {
    asm volatile("ldmatrix.sync.aligned.m8n8.x4.shared.b16 {%0,%1,%2,%3}, [%4];"
                 : "=r"(r0), "=r"(r1), "=r"(r2), "=r"(r3) : "r"(addr));
}
static __device__ __forceinline__ void ldsm_x4t(uint32_t& r0, uint32_t& r1, uint32_t& r2, uint32_t& r3, uint32_t addr) {
    asm volatile("ldmatrix.sync.aligned.m8n8.x4.trans.shared.b16 {%0,%1,%2,%3}, [%4];"
                 : "=r"(r0), "=r"(r1), "=r"(r2), "=r"(r3) : "r"(addr));
}
static __device__ __forceinline__ void mma16816(float* d, const uint32_t* a, const uint32_t* b) {
    asm volatile("mma.sync.aligned.m16n8k16.row.col.f32.f16.f16.f32 "
                 "{%0,%1,%2,%3}, {%4,%5,%6,%7}, {%8,%9}, {%0,%1,%2,%3};"
                 : "+f"(d[0]), "+f"(d[1]), "+f"(d[2]), "+f"(d[3])
                 : "r"(a[0]), "r"(a[1]), "r"(a[2]), "r"(a[3]), "r"(b[0]), "r"(b[1]));
}
static __device__ __forceinline__ uint4 cvt8(const float4 a0, const float4 a1) {
    __half2 h0 = __floats2half2_rn(a0.x, a0.y);
    __half2 h1 = __floats2half2_rn(a0.z, a0.w);
    __half2 h2 = __floats2half2_rn(a1.x, a1.y);
    __half2 h3 = __floats2half2_rn(a1.z, a1.w);
    uint4 v;
    v.x = *(uint32_t*)&h0; v.y = *(uint32_t*)&h1;
    v.z = *(uint32_t*)&h2; v.w = *(uint32_t*)&h3;
    return v;
}

// ---- prep: w fp32 [f][k][c] -> fp16 image [k][c][f], SW128 per 8KB tap tile --
__global__ void prep_w_kernel(const float* __restrict__ w) {
    int i = blockIdx.x * 256 + threadIdx.x;
    if (i < NF * KW * CIN) {
        int f = i / (KW * CIN);
        int k = (i / CIN) % KW;
        int c = i % CIN;
        *reinterpret_cast<__half*>(wt_img + k * 8192 + swz((uint32_t)(c * 128 + f * 2))) = __float2half_rn(w[i]);
    }
}

// ---- main persistent kernel: 16 warps, warp tile 32r x 64f -------------------
__global__ __launch_bounds__(NTHR, 1) void conv_hmma_kernel(const float* __restrict__ x,
                                                            const float* __restrict__ bias,
                                                            float* __restrict__ out) {
    extern __shared__ char smem_raw[];
    const uint32_t raw = smem_u32(smem_raw);
    const uint32_t sb  = (raw + 1023u) & ~1023u;
    char* base = smem_raw + (sb - raw);
    const int tid  = threadIdx.x;
    const int lane = tid & 31;
    const int warp_m = tid >> 5;                 // 16 M-warps, 32 rows each; all 64 f

    // copy w image + bias into smem (once)
    for (int i = tid; i < WS_BYTES / 16; i += NTHR)
        *(uint4*)(base + WS_OFF + i * 16) = *(const uint4*)(wt_img + i * 16);
    if (tid < NF) *(float*)(base + BIAS_OFF + tid * 4) = bias[tid];

    // ldmatrix lane address components
    const int row8   = (lane & 7) + ((lane >> 3) & 1) * 8;
    const int half16 = (lane >> 4);
    const uint32_t a_base = (uint32_t)(row8 * 128 + half16 * 16);
    const uint32_t b_base = (uint32_t)(row8 * 128 + half16 * 16);   // f offset via p*32
    const int g  = lane >> 2;
    const int tg = lane & 3;

    // ---- prologue: stage first tile fully (fp32 LDG -> cvt -> swizzled STS)
    {
        const int tile = blockIdx.x;
        const int t0 = (tile & 31) << 9;
        const float* xb = x + ((size_t)(tile >> 5) << 20);
        for (int q = tid; q < NCHUNK; q += NTHR) {
            const int r = q >> 3, c0 = (q & 7) << 3;
            const int t = t0 + r;
            uint4 v = make_uint4(0u, 0u, 0u, 0u);
            if (t < SEQ) {
                const float4 a0 = *(const float4*)(xb + (size_t)t * CIN + c0);
                const float4 a1 = *(const float4*)(xb + (size_t)t * CIN + c0 + 4);
                v = cvt8(a0, a1);
            }
            *(uint4*)(base + XS0_OFF + swz((uint32_t)(r * 128 + c0 * 2))) = v;
        }
    }
    __syncthreads();

    int buf = 0;
    for (int tile = blockIdx.x; tile < NTILES; tile += NCTA) {
        const int b  = tile >> 5;
        const int t0 = (tile & 31) << 9;
        const int nxt = tile + NCTA;
        const int have_nxt = nxt < NTILES;
        const int nt0 = (nxt & 31) << 9;
        const float* nxb = x + ((size_t)(nxt >> 5) << 20);

        const uint32_t xs = sb + (buf ? XS1_OFF : XS0_OFF);
        char* xd = base + (buf ? XS0_OFF : XS1_OFF);
        const uint32_t ws_addr = sb + WS_OFF;

        float acc[2][8][4];
#pragma unroll
        for (int mt = 0; mt < 2; mt++)
#pragma unroll
            for (int nt = 0; nt < 8; nt++)
#pragma unroll
                for (int j = 0; j < 4; j++) acc[mt][nt][j] = 0.0f;

#pragma unroll
        for (int k = 0; k < KW; k++) {
            // ---- issue next-tile staging loads: exactly 1 chunk/thread/tap
            float4 L0, L1;
            int rr = 0, cc0 = 0, lv = 0;
            if (have_nxt) {
                const int q = k * SLICE_CH + tid;
                if (tid < SLICE_CH && q < NCHUNK) {
                    const int r = q >> 3, c0 = (q & 7) << 3;
                    rr = r; cc0 = c0;
                    const int t = nt0 + r;
                    if (t < SEQ) {
                        L0 = *(const float4*)(nxb + (size_t)t * CIN + c0);
                        L1 = *(const float4*)(nxb + (size_t)t * CIN + c0 + 4);
                        lv = 2;
                    } else lv = 1;
                }
            }

            // ---- tap k: 4 c-chunks of m16n8k16, warp tile 32r x 64f
            const uint32_t a_row0 = (uint32_t)((warp_m * 32 + k) * 128);
            const uint32_t w_tap  = ws_addr + (uint32_t)(k * 8192);
#pragma unroll
            for (int cc = 0; cc < 4; cc++) {
                // all 6 shared loads up front: 4x B, 2x A
                uint32_t bf[8][2];
#pragma unroll
                for (int p = 0; p < 4; p++) {
                    const uint32_t off = (uint32_t)(cc * 16 * 128) + (uint32_t)(p * 32) + b_base;
                    uint32_t r0, r1, r2, r3;
                    ldsm_x4t(r0, r1, r2, r3, w_tap + swz(off));
                    bf[p * 2 + 0][0] = r0; bf[p * 2 + 0][1] = r1;
                    bf[p * 2 + 1][0] = r2; bf[p * 2 + 1][1] = r3;
                }
                uint32_t af[2][4];
#pragma unroll
                for (int mt = 0; mt < 2; mt++) {
                    const uint32_t off = a_row0 + (uint32_t)(mt * 16 * 128) + (uint32_t)(cc * 32) + a_base;
                    ldsm_x4(af[mt][0], af[mt][1], af[mt][2], af[mt][3], xs + swz(off));
                }
#pragma unroll
                for (int mt = 0; mt < 2; mt++)
#pragma unroll
                    for (int nt = 0; nt < 8; nt++)
                        mma16816(acc[mt][nt], af[mt], bf[nt]);
            }

            // ---- convert + store staged chunk into the other buffer
            if (lv) {
                uint4 v = make_uint4(0u, 0u, 0u, 0u);
                if (lv == 2) v = cvt8(L0, L1);
                *(uint4*)(xd + swz((uint32_t)(rr * 128 + cc0 * 2))) = v;
            }
        }

        // ---- epilogue: bias (from smem) + direct STG
#pragma unroll
        for (int mt = 0; mt < 2; mt++) {
            const int trow = t0 + warp_m * 32 + mt * 16 + g;
#pragma unroll
            for (int half = 0; half < 2; half++) {
                const int t = trow + half * 8;
                if (t < TOUT) {
                    float* o = out + ((size_t)b * TOUT + t) * NF;
#pragma unroll
                    for (int nt = 0; nt < 8; nt++) {
                        const float2 bv = *(const float2*)(base + BIAS_OFF + (nt * 8 + tg * 2) * 4);
                        float2 v;
                        v.x = acc[mt][nt][half * 2 + 0] + bv.x;
                        v.y = acc[mt][nt][half * 2 + 1] + bv.y;
                        *(float2*)(o + nt * 8 + tg * 2) = v;
                    }
                }
            }
        }
        __syncthreads();      // all reads of xs done AND all STS into xd visible
        buf ^= 1;
    }
}

extern "C" void kernel_launch(void* const* d_in, const int* in_sizes, int n_in,
                              void* d_out, int out_size) {
    const float* x    = (const float*)d_in[0];
    const float* w    = (const float*)d_in[1];
    const float* bias = (const float*)d_in[2];
    float* out = (float*)d_out;

    cudaFuncSetAttribute(conv_hmma_kernel, cudaFuncAttributeMaxDynamicSharedMemorySize, SMEM_BYTES);

    prep_w_kernel<<<(NF * KW * CIN + 255) / 256, 256>>>(w);
    conv_hmma_kernel<<<NCTA, NTHR, SMEM_BYTES>>>(x, bias, out);
}

// round 17
// speedup vs baseline: 1.3625x; 1.0984x over previous
#include <cuda_runtime.h>
#include <cuda_fp16.h>
#include <cstdint>

#define BATCH 32
#define SEQ   16384
#define CIN   64
#define NF    64
#define KW    9
#define TOUT  (SEQ - KW + 1)          // 16376
#define TTILE 512
#define TILES_PER_B 32
#define NTILES (BATCH * TILES_PER_B)  // 1024
#define XROWS (TTILE + KW - 1)        // 520
#define NCTA  148
#define NTHR  512
#define NCHUNK (XROWS * 8)            // 4160 16B-smem chunks per tile
#define SLICE_CH 464                  // chunks per tap-slice (9*464 >= 4160); <= NTHR

// smem layout (from 1024B-aligned base)
#define WS_OFF    0
#define WS_BYTES  (KW * 64 * 128)            // 73728: 9 taps of [64f x 128B(64c fp16)] SW128
#define XSB       (XROWS * 128)              // 66560
#define XS0_OFF   WS_BYTES                   // 73728
#define XS1_OFF   (XS0_OFF + XSB)            // 140288
#define BIAS_OFF  (XS1_OFF + XSB)            // 206848
#define SMEM_BYTES (BIAS_OFF + 256 + 1024)   // 208128 -> 1 CTA/SM

__device__ __align__(16) unsigned char wt_img[WS_BYTES];

static __device__ __forceinline__ uint32_t swz(uint32_t o) { return o ^ ((o >> 3) & 0x70); }

static __device__ __forceinline__ uint32_t smem_u32(const void* p) {
    uint32_t a;
    asm("{ .reg .u64 t; cvta.to.shared.u64 t, %1; cvt.u32.u64 %0, t; }" : "=r"(a) : "l"(p));
    return a;
}
static __device__ __forceinline__ void ldsm_x4(uint32_t& r0, uint32_t& r1, uint32_t& r2, uint32_t& r3, uint32_t addr) {
    asm volatile("ldmatrix.sync.aligned.m8n8.x4.shared.b16 {%0,%1,%2,%3}, [%4];"
                 : "=r"(r0), "=r"(r1), "=r"(r2), "=r"(r3) : "r"(addr));
}
static __device__ __forceinline__ void mma16816(float* d, const uint32_t* a, const uint32_t* b) {
    asm volatile("mma.sync.aligned.m16n8k16.row.col.f32.f16.f16.f32 "
                 "{%0,%1,%2,%3}, {%4,%5,%6,%7}, {%8,%9}, {%0,%1,%2,%3};"
                 : "+f"(d[0]), "+f"(d[1]), "+f"(d[2]), "+f"(d[3])
                 : "r"(a[0]), "r"(a[1]), "r"(a[2]), "r"(a[3]), "r"(b[0]), "r"(b[1]));
}
static __device__ __forceinline__ uint4 cvt8(const float4 a0, const float4 a1) {
    __half2 h0 = __floats2half2_rn(a0.x, a0.y);
    __half2 h1 = __floats2half2_rn(a0.z, a0.w);
    __half2 h2 = __floats2half2_rn(a1.x, a1.y);
    __half2 h3 = __floats2half2_rn(a1.z, a1.w);
    uint4 v;
    v.x = *(uint32_t*)&h0; v.y = *(uint32_t*)&h1;
    v.z = *(uint32_t*)&h2; v.w = *(uint32_t*)&h3;
    return v;
}

// ---- prep: w fp32 [f][k][c] -> fp16 image [k][f][c], SW128 per 8KB tap tile --
// (f-major rows so B fragments come from NON-trans ldmatrix)
__global__ void prep_w_kernel(const float* __restrict__ w) {
    int i = blockIdx.x * 256 + threadIdx.x;
    if (i < NF * KW * CIN) {
        int f = i / (KW * CIN);
        int k = (i / CIN) % KW;
        int c = i % CIN;
        *reinterpret_cast<__half*>(wt_img + k * 8192 + swz((uint32_t)(f * 128 + c * 2))) = __float2half_rn(w[i]);
    }
}

// ---- main persistent kernel: 16 warps, warp tile 32r x 64f -------------------
__global__ __launch_bounds__(NTHR, 1) void conv_hmma_kernel(const float* __restrict__ x,
                                                            const float* __restrict__ bias,
                                                            float* __restrict__ out) {
    extern __shared__ char smem_raw[];
    const uint32_t raw = smem_u32(smem_raw);
    const uint32_t sb  = (raw + 1023u) & ~1023u;
    char* base = smem_raw + (sb - raw);
    const int tid  = threadIdx.x;
    const int lane = tid & 31;
    const int warp_m = tid >> 5;                 // 16 M-warps, 32 rows each; all 64 f

    // copy w image + bias into smem (once)
    for (int i = tid; i < WS_BYTES / 16; i += NTHR)
        *(uint4*)(base + WS_OFF + i * 16) = *(const uint4*)(wt_img + i * 16);
    if (tid < NF) *(float*)(base + BIAS_OFF + tid * 4) = bias[tid];

    // ldmatrix lane address components
    // A (x tile, row-major t x c): rows 0..15 from lanes 0-15, c-half from lane>>4
    const int row8   = (lane & 7) + ((lane >> 3) & 1) * 8;
    const int half16 = (lane >> 4);
    const uint32_t a_base = (uint32_t)(row8 * 128 + half16 * 16);
    // B (w tile, f-row x c-col, non-trans): f = (lane>>4)*8 + (lane&7), c-half from lane bit3
    const int bf_row = ((lane >> 4) & 1) * 8 + (lane & 7);
    const uint32_t b_base = (uint32_t)(bf_row * 128 + ((lane >> 3) & 1) * 16);
    const int g  = lane >> 2;
    const int tg = lane & 3;

    // ---- prologue: stage first tile fully (fp32 LDG -> cvt -> swizzled STS)
    {
        const int tile = blockIdx.x;
        const int t0 = (tile & 31) << 9;
        const float* xb = x + ((size_t)(tile >> 5) << 20);
        for (int q = tid; q < NCHUNK; q += NTHR) {
            const int r = q >> 3, c0 = (q & 7) << 3;
            const int t = t0 + r;
            uint4 v = make_uint4(0u, 0u, 0u, 0u);
            if (t < SEQ) {
                const float4 a0 = *(const float4*)(xb + (size_t)t * CIN + c0);
                const float4 a1 = *(const float4*)(xb + (size_t)t * CIN + c0 + 4);
                v = cvt8(a0, a1);
            }
            *(uint4*)(base + XS0_OFF + swz((uint32_t)(r * 128 + c0 * 2))) = v;
        }
    }
    __syncthreads();

    int buf = 0;
    for (int tile = blockIdx.x; tile < NTILES; tile += NCTA) {
        const int b  = tile >> 5;
        const int t0 = (tile & 31) << 9;
        const int nxt = tile + NCTA;
        const int have_nxt = nxt < NTILES;
        const int nt0 = (nxt & 31) << 9;
        const float* nxb = x + ((size_t)(nxt >> 5) << 20);

        const uint32_t xs = sb + (buf ? XS1_OFF : XS0_OFF);
        char* xd = base + (buf ? XS0_OFF : XS1_OFF);
        const uint32_t ws_addr = sb + WS_OFF;

        float acc[2][8][4];
#pragma unroll
        for (int mt = 0; mt < 2; mt++)
#pragma unroll
            for (int nt = 0; nt < 8; nt++)
#pragma unroll
                for (int j = 0; j < 4; j++) acc[mt][nt][j] = 0.0f;

        for (int k = 0; k < KW; k++) {
            // ---- issue next-tile staging loads: exactly 1 chunk/thread/tap
            float4 L0, L1;
            int rr = 0, cc0 = 0, lv = 0;
            if (have_nxt) {
                const int q = k * SLICE_CH + tid;
                if (tid < SLICE_CH && q < NCHUNK) {
                    const int r = q >> 3, c0 = (q & 7) << 3;
                    rr = r; cc0 = c0;
                    const int t = nt0 + r;
                    if (t < SEQ) {
                        L0 = *(const float4*)(nxb + (size_t)t * CIN + c0);
                        L1 = *(const float4*)(nxb + (size_t)t * CIN + c0 + 4);
                        lv = 2;
                    } else lv = 1;
                }
            }

            // ---- tap k: 4 c-chunks of m16n8k16, warp tile 32r x 64f
            const uint32_t a_row0 = (uint32_t)((warp_m * 32 + k) * 128);
            const uint32_t w_tap  = ws_addr + (uint32_t)(k * 8192);
#pragma unroll
            for (int cc = 0; cc < 4; cc++) {
                uint32_t bf[8][2];
#pragma unroll
                for (int p = 0; p < 4; p++) {
                    // non-trans: block covers f rows [p*16, p*16+16), c halves [cc*16, cc*16+16)
                    const uint32_t off = (uint32_t)(p * 16 * 128) + (uint32_t)(cc * 32) + b_base;
                    uint32_t r0, r1, r2, r3;
                    ldsm_x4(r0, r1, r2, r3, w_tap + swz(off));
                    bf[p * 2 + 0][0] = r0; bf[p * 2 + 0][1] = r1;   // nt = p*2   (f p*16..+7)
                    bf[p * 2 + 1][0] = r2; bf[p * 2 + 1][1] = r3;   // nt = p*2+1 (f p*16+8..+15)
                }
#pragma unroll
                for (int mt = 0; mt < 2; mt++) {
                    uint32_t af[4];
                    const uint32_t off = a_row0 + (uint32_t)(mt * 16 * 128) + (uint32_t)(cc * 32) + a_base;
                    ldsm_x4(af[0], af[1], af[2], af[3], xs + swz(off));
#pragma unroll
                    for (int nt = 0; nt < 8; nt++)
                        mma16816(acc[mt][nt], af, bf[nt]);
                }
            }

            // ---- convert + store staged chunk into the other buffer
            if (lv) {
                uint4 v = make_uint4(0u, 0u, 0u, 0u);
                if (lv == 2) v = cvt8(L0, L1);
                *(uint4*)(xd + swz((uint32_t)(rr * 128 + cc0 * 2))) = v;
            }
        }

        // ---- epilogue: bias (from smem) + direct STG
#pragma unroll
        for (int mt = 0; mt < 2; mt++) {
            const int trow = t0 + warp_m * 32 + mt * 16 + g;
#pragma unroll
            for (int half = 0; half < 2; half++) {
                const int t = trow + half * 8;
                if (t < TOUT) {
                    float* o = out + ((size_t)b * TOUT + t) * NF;
#pragma unroll
                    for (int nt = 0; nt < 8; nt++) {
                        const float2 bv = *(const float2*)(base + BIAS_OFF + (nt * 8 + tg * 2) * 4);
                        float2 v;
                        v.x = acc[mt][nt][half * 2 + 0] + bv.x;
                        v.y = acc[mt][nt][half * 2 + 1] + bv.y;
                        *(float2*)(o + nt * 8 + tg * 2) = v;
                    }
                }
            }
        }
        __syncthreads();      // all reads of xs done AND all STS into xd visible
        buf ^= 1;
    }
}

extern "C" void kernel_launch(void* const* d_in, const int* in_sizes, int n_in,
                              void* d_out, int out_size) {
    const float* x    = (const float*)d_in[0];
    const float* w    = (const float*)d_in[1];
    const float* bias = (const float*)d_in[2];
    float* out = (float*)d_out;

    cudaFuncSetAttribute(conv_hmma_kernel, cudaFuncAttributeMaxDynamicSharedMemorySize, SMEM_BYTES);

    prep_w_kernel<<<(NF * KW * CIN + 255) / 256, 256>>>(w);
    conv_hmma_kernel<<<NCTA, NTHR, SMEM_BYTES>>>(x, bias, out);
}